// round 15
// baseline (speedup 1.0000x reference)
#include <cuda_runtime.h>
#include <cuda_fp16.h>
#include <cstdint>

#define NN   8192
#define FIN  256
#define FOUT 128

// ---------------- device scratch ----------------
__device__ __align__(16) __half g_Wh[NN * FOUT];       // [j][f] fp16
__device__ __align__(16) float  g_num[4 * NN * FOUT];  // 4-way split-j partials
__device__ float  g_den[4 * NN];
__device__ __align__(16) float4 g_e1[NN];              // (e^s1, e^{0.2 s1}, s1, 0)
__device__ __align__(16) uint4  g_lut[NN / 2];         // per j-pair: {e2p2, e2n2, s22, 0}

// ---------------- helpers ----------------
__device__ __forceinline__ uint32_t smem_u32(const void* p) {
    uint32_t a;
    asm("{ .reg .u64 t; cvta.to.shared.u64 t, %1; cvt.u32.u64 %0, t; }" : "=r"(a) : "l"(p));
    return a;
}
__device__ __forceinline__ void ldsm_x4(uint32_t* r, uint32_t addr) {
    asm volatile("ldmatrix.sync.aligned.m8n8.x4.shared.b16 {%0,%1,%2,%3}, [%4];"
                 : "=r"(r[0]), "=r"(r[1]), "=r"(r[2]), "=r"(r[3]) : "r"(addr));
}
__device__ __forceinline__ void ldsm_x4_t(uint32_t* r, uint32_t addr) {
    asm volatile("ldmatrix.sync.aligned.m8n8.x4.trans.shared.b16 {%0,%1,%2,%3}, [%4];"
                 : "=r"(r[0]), "=r"(r[1]), "=r"(r[2]), "=r"(r[3]) : "r"(addr));
}
__device__ __forceinline__ void mma_f16(float* d, const uint32_t* a, uint32_t b0, uint32_t b1) {
    asm volatile(
        "mma.sync.aligned.m16n8k16.row.col.f32.f16.f16.f32 "
        "{%0,%1,%2,%3}, {%4,%5,%6,%7}, {%8,%9}, {%0,%1,%2,%3};"
        : "+f"(d[0]), "+f"(d[1]), "+f"(d[2]), "+f"(d[3])
        : "r"(a[0]), "r"(a[1]), "r"(a[2]), "r"(a[3]), "r"(b0), "r"(b1));
}
__device__ __forceinline__ void cp_async16(uint32_t dst, const void* src) {
    asm volatile("cp.async.cg.shared.global [%0], [%1], 16;" :: "r"(dst), "l"(src));
}
#define CP_COMMIT() asm volatile("cp.async.commit_group;" ::: "memory")
#define CP_WAIT0()  asm volatile("cp.async.wait_group 0;" ::: "memory")
__device__ __forceinline__ uint32_t h2u(__half2 h) { return *(uint32_t*)&h; }
__device__ __forceinline__ uint32_t bcast_h2(float f) {
    __half2 v = __float2half2_rn(f);
    return *(uint32_t*)&v;
}
__device__ __forceinline__ uint32_t adj_mask(int2 a) {
    return (uint32_t)a.x * 0xFFFFu + (uint32_t)a.y * 0xFFFF0000u;
}
__device__ __forceinline__ uint32_t genA2(uint32_t e2p2, uint32_t e2n2, uint32_t s22,
                                          uint32_t r, uint32_t ns1, uint32_t am) {
    uint32_t pn, mk;
    asm("mul.f16x2 %0, %1, %2;" : "=r"(pn) : "r"(r), "r"(e2n2));
    asm("set.ge.u32.f16x2 %0, %1, %2;" : "=r"(mk) : "r"(s22), "r"(ns1));
    return (((e2p2 & mk) | (pn & ~mk)) & am);
}
__device__ __forceinline__ void hadd2_acc(uint32_t& acc, uint32_t v) {
    asm("add.rn.f16x2 %0, %0, %1;" : "+r"(acc) : "r"(v));
}

// ---------------- Kernel 1: Wh = h@W (h fp16, W hi+lo), e1/lut, Wh ----------------
#define R1H 528
#define R1W 272
#define HH_OFF 0
#define WH_OFF (64 * R1H)
#define WL_OFF (WH_OFF + 256 * R1W)
#define K1_SMEM (WL_OFF + 256 * R1W)
#define AVEC_OFF (64 * 132 * 4)

__global__ __launch_bounds__(512, 1) void k1_gemm_s(
    const float* __restrict__ h, const float* __restrict__ W,
    const float* __restrict__ a)
{
    extern __shared__ char base[];
    const uint32_t sb = smem_u32(base);
    const int t = threadIdx.x, lane = t & 31, w = t >> 5;
    const int row0 = blockIdx.x * 64;

    // stage h (64x256) single fp16
#pragma unroll
    for (int p = 0; p < 8; p++) {
        int id = t + p * 512;
        int r = id >> 6, c4 = id & 63;
        float4 v = *(const float4*)&h[(size_t)(row0 + r) * FIN + c4 * 4];
        __half2 hp0, hp1;
        hp0.x = __float2half_rn(v.x); hp0.y = __float2half_rn(v.y);
        hp1.x = __float2half_rn(v.z); hp1.y = __float2half_rn(v.w);
        *(uint2*)(base + HH_OFF + (uint32_t)r * R1H + c4 * 8) =
            make_uint2(h2u(hp0), h2u(hp1));
    }
    // stage W (256x128) fp16 hi/lo, [k][f]
#pragma unroll
    for (int p = 0; p < 16; p++) {
        int id = t + p * 512;
        int k = id >> 5, f4 = id & 31;
        float4 v = *(const float4*)&W[(size_t)k * FOUT + f4 * 4];
        __half x0 = __float2half_rn(v.x), x1 = __float2half_rn(v.y);
        __half x2 = __float2half_rn(v.z), x3 = __float2half_rn(v.w);
        __half2 hp0, hp1, lp0, lp1;
        hp0.x = x0; hp0.y = x1; hp1.x = x2; hp1.y = x3;
        lp0.x = __float2half_rn(v.x - __half2float(x0));
        lp0.y = __float2half_rn(v.y - __half2float(x1));
        lp1.x = __float2half_rn(v.z - __half2float(x2));
        lp1.y = __float2half_rn(v.w - __half2float(x3));
        uint32_t off = (uint32_t)k * R1W + f4 * 8;
        *(uint2*)(base + WH_OFF + off) = make_uint2(h2u(hp0), h2u(hp1));
        *(uint2*)(base + WL_OFF + off) = make_uint2(h2u(lp0), h2u(lp1));
    }
    __syncthreads();

    const int mrow0 = (w & 3) * 16;
    const int ncol0 = (w >> 2) * 32;
    float acc[16];
#pragma unroll
    for (int q = 0; q < 16; q++) acc[q] = 0.0f;

    const uint32_t aH = sb + HH_OFF + (uint32_t)(mrow0 + (lane & 15)) * R1H + (lane >> 4) * 16;

#pragma unroll
    for (int ks = 0; ks < 16; ks++) {
        uint32_t Ah[4];
        ldsm_x4(Ah, aH + ks * 32);
#pragma unroll
        for (int ng = 0; ng < 2; ng++) {
            uint32_t bo = (uint32_t)(ks * 16 + (lane & 15)) * R1W +
                          (ncol0 + ng * 16 + (lane >> 4) * 8) * 2;
            uint32_t Bh[4], Bl[4];
            ldsm_x4_t(Bh, sb + WH_OFF + bo);
            ldsm_x4_t(Bl, sb + WL_OFF + bo);
#pragma unroll
            for (int s = 0; s < 2; s++) {
                float* d = &acc[(ng * 2 + s) * 4];
                mma_f16(d, Ah, Bh[s * 2], Bh[s * 2 + 1]);
                mma_f16(d, Ah, Bl[s * 2], Bl[s * 2 + 1]);
            }
        }
    }
    __syncthreads();

    float* stage = (float*)base;
    float* a_s   = (float*)(base + AVEC_OFF);
#pragma unroll
    for (int nb = 0; nb < 4; nb++) {
        const float* d = &acc[nb * 4];
        int row = mrow0 + (lane >> 2);
        int col = ncol0 + (nb >> 1) * 16 + (nb & 1) * 8 + (lane & 3) * 2;
        stage[row * 132 + col]     = d[0];
        stage[row * 132 + col + 1] = d[1];
        stage[(row + 8) * 132 + col]     = d[2];
        stage[(row + 8) * 132 + col + 1] = d[3];
    }
    if (t < 256) a_s[t] = a[t];
    __syncthreads();

    if (t < 64) {
        float p1 = 0.f, p2 = 0.f;
#pragma unroll 8
        for (int c = 0; c < 128; c++) {
            float v = stage[t * 132 + c];
            p1 = fmaf(v, a_s[c], p1);
            p2 = fmaf(v, a_s[128 + c], p2);
        }
        g_e1[row0 + t] = make_float4(__expf(p1), __expf(0.2f * p1), p1, 0.0f);
        float e2p = __expf(p2), e2n = __expf(0.2f * p2);
        float e2p_n = __shfl_down_sync(0xffffffffu, e2p, 1);
        float e2n_n = __shfl_down_sync(0xffffffffu, e2n, 1);
        float s2_n  = __shfl_down_sync(0xffffffffu, p2, 1);
        if ((t & 1) == 0) {
            __half2 a0 = __floats2half2_rn(e2p, e2p_n);
            __half2 b0 = __floats2half2_rn(e2n, e2n_n);
            __half2 c0 = __floats2half2_rn(p2, s2_n);
            uint4 e;
            e.x = h2u(a0); e.y = h2u(b0); e.z = h2u(c0); e.w = 0;
            g_lut[(row0 + t) >> 1] = e;
        }
    }
    {
        int row = t >> 3;
        int f0  = (t & 7) * 16;
#pragma unroll
        for (int q = 0; q < 8; q++) {
            __half2 hp;
            hp.x = __float2half_rn(stage[row * 132 + f0 + q * 2]);
            hp.y = __float2half_rn(stage[row * 132 + f0 + q * 2 + 1]);
            *(__half2*)&g_Wh[(size_t)(row0 + row) * FOUT + f0 + q * 2] = hp;
        }
    }
}

// ---------------- Kernel 2: den via HADD2 (no ones-mma) ----------------
// 256 CTAs = 64 i-tiles (128 rows) x 4 j-quarters; 256 thr, 2 CTAs/SM.
#define RB     272
#define BTILE  (128 * RB)
#define LUT_OFF (2 * BTILE)
#define K2_SMEM (LUT_OFF + 2048 + 256)

__global__ __launch_bounds__(256, 2) void k2_attn(const int* __restrict__ adj)
{
    extern __shared__ char base[];
    const uint32_t sb = smem_u32(base);

    const int t = threadIdx.x, lane = t & 31, w = t >> 5;   // 8 warps
    const int i0   = (blockIdx.x >> 2) * 128;
    const int q    = blockIdx.x & 3;
    const int jbeg = q * 2048;

    const int mrow0 = w * 16;
    const int cq    = (lane & 3) * 2;

    const int gr0 = i0 + mrow0 + (lane >> 2);
    const int gr1 = gr0 + 8;
    const float4 E0 = g_e1[gr0];
    const float4 E1 = g_e1[gr1];
    const uint32_t rr0 = bcast_h2(E0.y / E0.x), ns10 = bcast_h2(-E0.z);
    const uint32_t rr1 = bcast_h2(E1.y / E1.x), ns11 = bcast_h2(-E1.z);

    float acc[64];
#pragma unroll
    for (int z = 0; z < 64; z++) acc[z] = 0.0f;
    float dd0 = 0.0f, dd1 = 0.0f;          // fp32 den accumulators

    const int bj = t >> 4;
    const int bc = t & 15;

    // ---- prologue ----
    {
#pragma unroll
        for (int p = 0; p < 8; p++) {
            int j = bj + p * 16;
            cp_async16(sb + (uint32_t)j * RB + bc * 16,
                       &g_Wh[(size_t)(jbeg + j) * FOUT + bc * 8]);
        }
        if (t < 64)
            cp_async16(sb + LUT_OFF + t * 16, &g_lut[(jbeg >> 1) + t]);
        CP_COMMIT();
    }
    uint32_t aq[2][4];
#pragma unroll
    for (int s = 0; s < 2; s++) {
        int jc = jbeg + s * 16 + cq;
        aq[s][0] = adj_mask(*(const int2*)&adj[(size_t)gr0 * NN + jc]);
        aq[s][1] = adj_mask(*(const int2*)&adj[(size_t)gr1 * NN + jc]);
        aq[s][2] = adj_mask(*(const int2*)&adj[(size_t)gr0 * NN + jc + 8]);
        aq[s][3] = adj_mask(*(const int2*)&adj[(size_t)gr1 * NN + jc + 8]);
    }
    CP_WAIT0();
    __syncthreads();

    // ---- main loop: 16 tiles of 128 j ----
    for (int it = 0; it < 16; it++) {
        const uint32_t bbuf = sb + (uint32_t)(it & 1) * BTILE;
        const uint32_t loff = LUT_OFF + (uint32_t)(it & 1) * 1024;

        if (it < 15) {
            const int j0n = jbeg + (it + 1) * 128;
            const uint32_t nb = sb + (uint32_t)((it + 1) & 1) * BTILE;
#pragma unroll
            for (int p = 0; p < 8; p++) {
                int j = bj + p * 16;
                cp_async16(nb + (uint32_t)j * RB + bc * 16,
                           &g_Wh[(size_t)(j0n + j) * FOUT + bc * 8]);
            }
            if (t < 64)
                cp_async16(sb + LUT_OFF + (uint32_t)((it + 1) & 1) * 1024 + t * 16,
                           &g_lut[(j0n >> 1) + t]);
            CP_COMMIT();
        }

        uint32_t dh0 = 0, dh1 = 0;          // per-tile f16x2 den partials
#pragma unroll
        for (int ks = 0; ks < 8; ks++) {
            uint4 L0 = *(const uint4*)(base + loff + (ks * 8 + (lane & 3)) * 16);
            uint4 L1 = *(const uint4*)(base + loff + (ks * 8 + (lane & 3) + 4) * 16);

            uint32_t A[4];
            A[0] = genA2(L0.x, L0.y, L0.z, rr0, ns10, aq[ks & 1][0]);
            A[1] = genA2(L0.x, L0.y, L0.z, rr1, ns11, aq[ks & 1][1]);
            A[2] = genA2(L1.x, L1.y, L1.z, rr0, ns10, aq[ks & 1][2]);
            A[3] = genA2(L1.x, L1.y, L1.z, rr1, ns11, aq[ks & 1][3]);

            {
                int ksg2 = it * 8 + ks + 2;
                if (ksg2 > 127) ksg2 = 127;
                int jc = jbeg + (ksg2 >> 3) * 128 + (ksg2 & 7) * 16 + cq;
                aq[ks & 1][0] = adj_mask(*(const int2*)&adj[(size_t)gr0 * NN + jc]);
                aq[ks & 1][1] = adj_mask(*(const int2*)&adj[(size_t)gr1 * NN + jc]);
                aq[ks & 1][2] = adj_mask(*(const int2*)&adj[(size_t)gr0 * NN + jc + 8]);
                aq[ks & 1][3] = adj_mask(*(const int2*)&adj[(size_t)gr1 * NN + jc + 8]);
            }

            // den partials on the fma pipe (replaces the ones-column mma)
            hadd2_acc(dh0, A[0]);
            hadd2_acc(dh0, A[2]);
            hadd2_acc(dh1, A[1]);
            hadd2_acc(dh1, A[3]);

#pragma unroll
            for (int ng = 0; ng < 8; ng++) {
                uint32_t B[4];
                uint32_t bo = (uint32_t)(ks * 16 + (lane & 15)) * RB +
                              (ng * 16 + (lane >> 4) * 8) * 2;
                ldsm_x4_t(B, bbuf + bo);
                mma_f16(&acc[(ng * 2) * 4],     A, B[0], B[1]);
                mma_f16(&acc[(ng * 2 + 1) * 4], A, B[2], B[3]);
            }
        }
        // dump per-tile den partials to fp32 (bounded magnitude per tile)
        {
            float2 f0 = __half22float2(*(__half2*)&dh0);
            float2 f1 = __half22float2(*(__half2*)&dh1);
            dd0 += f0.x + f0.y;
            dd1 += f1.x + f1.y;
        }
        CP_WAIT0();
        __syncthreads();
    }

    // ---- den: quad reduce, one writer ----
    dd0 += __shfl_xor_sync(0xffffffffu, dd0, 1);
    dd0 += __shfl_xor_sync(0xffffffffu, dd0, 2);
    dd1 += __shfl_xor_sync(0xffffffffu, dd1, 1);
    dd1 += __shfl_xor_sync(0xffffffffu, dd1, 2);
    if ((lane & 3) == 0) {
        g_den[(size_t)q * NN + gr0] = dd0;
        g_den[(size_t)q * NN + gr1] = dd1;
    }

    // ---- numerator writeout ----
#pragma unroll
    for (int nb = 0; nb < 16; nb++) {
        const float* d = &acc[nb * 4];
        int col = nb * 8 + cq;
        size_t o0 = ((size_t)q * NN + gr0) * FOUT + col;
        size_t o1 = ((size_t)q * NN + gr1) * FOUT + col;
        *(float2*)&g_num[o0] = make_float2(d[0], d[1]);
        *(float2*)&g_num[o1] = make_float2(d[2], d[3]);
    }
}

// ---------------- Kernel 3: combine 4 partials (2 float4/thread) ----------------
__global__ __launch_bounds__(256) void k3_combine(float* __restrict__ out)
{
    const size_t STR = (size_t)NN * FOUT;
    int b = blockIdx.x * 512 + threadIdx.x;
#pragma unroll
    for (int v = 0; v < 2; v++) {
        int idx = b + v * 256;
        int i = idx >> 5;
        float inv = 1.0f / ((g_den[i] + g_den[NN + i]) +
                            (g_den[2 * NN + i] + g_den[3 * NN + i]));
        float4 a0 = *(const float4*)&g_num[(size_t)idx * 4];
        float4 a1 = *(const float4*)&g_num[STR + (size_t)idx * 4];
        float4 a2 = *(const float4*)&g_num[2 * STR + (size_t)idx * 4];
        float4 a3 = *(const float4*)&g_num[3 * STR + (size_t)idx * 4];
        float4 o;
        o.x = ((a0.x + a1.x) + (a2.x + a3.x)) * inv;
        o.y = ((a0.y + a1.y) + (a2.y + a3.y)) * inv;
        o.z = ((a0.z + a1.z) + (a2.z + a3.z)) * inv;
        o.w = ((a0.w + a1.w) + (a2.w + a3.w)) * inv;
        *(float4*)&out[(size_t)idx * 4] = o;
    }
}

// ---------------- launcher ----------------
extern "C" void kernel_launch(void* const* d_in, const int* in_sizes, int n_in,
                              void* d_out, int out_size)
{
    const float* h   = (const float*)d_in[0];
    const int*   adj = (const int*)  d_in[1];
    const float* W   = (const float*)d_in[2];
    const float* a   = (const float*)d_in[3];
    float* out = (float*)d_out;
    (void)in_sizes; (void)n_in; (void)out_size;

    cudaFuncSetAttribute(k1_gemm_s, cudaFuncAttributeMaxDynamicSharedMemorySize, K1_SMEM);
    cudaFuncSetAttribute(k2_attn,  cudaFuncAttributeMaxDynamicSharedMemorySize, K2_SMEM);

    k1_gemm_s<<<NN / 64, 512, K1_SMEM>>>(h, W, a);
    k2_attn<<<(NN / 128) * 4, 256, K2_SMEM>>>(adj);
    k3_combine<<<NN * FOUT / 4 / 512, 256>>>(out);
}

// round 16
// speedup vs baseline: 1.1427x; 1.1427x over previous
#include <cuda_runtime.h>
#include <cuda_fp16.h>
#include <cstdint>

#define NN   8192
#define FIN  256
#define FOUT 128

// ---------------- device scratch ----------------
__device__ __align__(16) __half g_Wh[NN * FOUT];       // [j][f] fp16
__device__ __align__(16) float  g_num[4 * NN * FOUT];  // 4-way split-j partials
__device__ float  g_den[4 * NN];
__device__ __align__(16) float4 g_e1[NN];              // (e^s1, e^{0.2 s1}, s1, 0)
__device__ __align__(8)  uint2  g_lut[NN / 2];         // per j-pair: {e2p2, e2n2}

// ---------------- helpers ----------------
__device__ __forceinline__ uint32_t smem_u32(const void* p) {
    uint32_t a;
    asm("{ .reg .u64 t; cvta.to.shared.u64 t, %1; cvt.u32.u64 %0, t; }" : "=r"(a) : "l"(p));
    return a;
}
__device__ __forceinline__ void ldsm_x4(uint32_t* r, uint32_t addr) {
    asm volatile("ldmatrix.sync.aligned.m8n8.x4.shared.b16 {%0,%1,%2,%3}, [%4];"
                 : "=r"(r[0]), "=r"(r[1]), "=r"(r[2]), "=r"(r[3]) : "r"(addr));
}
__device__ __forceinline__ void ldsm_x4_t(uint32_t* r, uint32_t addr) {
    asm volatile("ldmatrix.sync.aligned.m8n8.x4.trans.shared.b16 {%0,%1,%2,%3}, [%4];"
                 : "=r"(r[0]), "=r"(r[1]), "=r"(r[2]), "=r"(r[3]) : "r"(addr));
}
__device__ __forceinline__ void mma_f16(float* d, const uint32_t* a, uint32_t b0, uint32_t b1) {
    asm volatile(
        "mma.sync.aligned.m16n8k16.row.col.f32.f16.f16.f32 "
        "{%0,%1,%2,%3}, {%4,%5,%6,%7}, {%8,%9}, {%0,%1,%2,%3};"
        : "+f"(d[0]), "+f"(d[1]), "+f"(d[2]), "+f"(d[3])
        : "r"(a[0]), "r"(a[1]), "r"(a[2]), "r"(a[3]), "r"(b0), "r"(b1));
}
__device__ __forceinline__ void cp_async16(uint32_t dst, const void* src) {
    asm volatile("cp.async.cg.shared.global [%0], [%1], 16;" :: "r"(dst), "l"(src));
}
#define CP_COMMIT() asm volatile("cp.async.commit_group;" ::: "memory")
#define CP_WAIT0()  asm volatile("cp.async.wait_group 0;" ::: "memory")
__device__ __forceinline__ uint32_t h2u(__half2 h) { return *(uint32_t*)&h; }
__device__ __forceinline__ uint32_t bcast_h2(float f) {
    __half2 v = __float2half2_rn(f);
    return *(uint32_t*)&v;
}
__device__ __forceinline__ uint32_t adj_mask(int2 a) {
    return (uint32_t)a.x * 0xFFFFu + (uint32_t)a.y * 0xFFFF0000u;
}
// A-frag gen via max identity: e^{lrelu(x)-s1} = max(e2p, r*e2n).
// 1 mul + 1 max + 1 and; no compare/select, no s2 operand.
__device__ __forceinline__ uint32_t genA3(uint32_t e2p2, uint32_t e2n2,
                                          uint32_t r, uint32_t am) {
    uint32_t pn, p;
    asm("mul.f16x2 %0, %1, %2;" : "=r"(pn) : "r"(r), "r"(e2n2));
    asm("max.f16x2 %0, %1, %2;" : "=r"(p) : "r"(pn), "r"(e2p2));
    return p & am;
}

// ---------------- Kernel 1: Wh = h@W (h fp16, W hi+lo), e1/lut, Wh ----------------
#define R1H 528
#define R1W 272
#define HH_OFF 0
#define WH_OFF (64 * R1H)
#define WL_OFF (WH_OFF + 256 * R1W)
#define K1_SMEM (WL_OFF + 256 * R1W)
#define AVEC_OFF (64 * 132 * 4)

__global__ __launch_bounds__(512, 1) void k1_gemm_s(
    const float* __restrict__ h, const float* __restrict__ W,
    const float* __restrict__ a)
{
    extern __shared__ char base[];
    const uint32_t sb = smem_u32(base);
    const int t = threadIdx.x, lane = t & 31, w = t >> 5;
    const int row0 = blockIdx.x * 64;

    // stage h (64x256) single fp16
#pragma unroll
    for (int p = 0; p < 8; p++) {
        int id = t + p * 512;
        int r = id >> 6, c4 = id & 63;
        float4 v = *(const float4*)&h[(size_t)(row0 + r) * FIN + c4 * 4];
        __half2 hp0, hp1;
        hp0.x = __float2half_rn(v.x); hp0.y = __float2half_rn(v.y);
        hp1.x = __float2half_rn(v.z); hp1.y = __float2half_rn(v.w);
        *(uint2*)(base + HH_OFF + (uint32_t)r * R1H + c4 * 8) =
            make_uint2(h2u(hp0), h2u(hp1));
    }
    // stage W (256x128) fp16 hi/lo, [k][f]
#pragma unroll
    for (int p = 0; p < 16; p++) {
        int id = t + p * 512;
        int k = id >> 5, f4 = id & 31;
        float4 v = *(const float4*)&W[(size_t)k * FOUT + f4 * 4];
        __half x0 = __float2half_rn(v.x), x1 = __float2half_rn(v.y);
        __half x2 = __float2half_rn(v.z), x3 = __float2half_rn(v.w);
        __half2 hp0, hp1, lp0, lp1;
        hp0.x = x0; hp0.y = x1; hp1.x = x2; hp1.y = x3;
        lp0.x = __float2half_rn(v.x - __half2float(x0));
        lp0.y = __float2half_rn(v.y - __half2float(x1));
        lp1.x = __float2half_rn(v.z - __half2float(x2));
        lp1.y = __float2half_rn(v.w - __half2float(x3));
        uint32_t off = (uint32_t)k * R1W + f4 * 8;
        *(uint2*)(base + WH_OFF + off) = make_uint2(h2u(hp0), h2u(hp1));
        *(uint2*)(base + WL_OFF + off) = make_uint2(h2u(lp0), h2u(lp1));
    }
    __syncthreads();

    const int mrow0 = (w & 3) * 16;
    const int ncol0 = (w >> 2) * 32;
    float acc[16];
#pragma unroll
    for (int q = 0; q < 16; q++) acc[q] = 0.0f;

    const uint32_t aH = sb + HH_OFF + (uint32_t)(mrow0 + (lane & 15)) * R1H + (lane >> 4) * 16;

#pragma unroll
    for (int ks = 0; ks < 16; ks++) {
        uint32_t Ah[4];
        ldsm_x4(Ah, aH + ks * 32);
#pragma unroll
        for (int ng = 0; ng < 2; ng++) {
            uint32_t bo = (uint32_t)(ks * 16 + (lane & 15)) * R1W +
                          (ncol0 + ng * 16 + (lane >> 4) * 8) * 2;
            uint32_t Bh[4], Bl[4];
            ldsm_x4_t(Bh, sb + WH_OFF + bo);
            ldsm_x4_t(Bl, sb + WL_OFF + bo);
#pragma unroll
            for (int s = 0; s < 2; s++) {
                float* d = &acc[(ng * 2 + s) * 4];
                mma_f16(d, Ah, Bh[s * 2], Bh[s * 2 + 1]);
                mma_f16(d, Ah, Bl[s * 2], Bl[s * 2 + 1]);
            }
        }
    }
    __syncthreads();

    float* stage = (float*)base;
    float* a_s   = (float*)(base + AVEC_OFF);
#pragma unroll
    for (int nb = 0; nb < 4; nb++) {
        const float* d = &acc[nb * 4];
        int row = mrow0 + (lane >> 2);
        int col = ncol0 + (nb >> 1) * 16 + (nb & 1) * 8 + (lane & 3) * 2;
        stage[row * 132 + col]     = d[0];
        stage[row * 132 + col + 1] = d[1];
        stage[(row + 8) * 132 + col]     = d[2];
        stage[(row + 8) * 132 + col + 1] = d[3];
    }
    if (t < 256) a_s[t] = a[t];
    __syncthreads();

    if (t < 64) {
        float p1 = 0.f, p2 = 0.f;
#pragma unroll 8
        for (int c = 0; c < 128; c++) {
            float v = stage[t * 132 + c];
            p1 = fmaf(v, a_s[c], p1);
            p2 = fmaf(v, a_s[128 + c], p2);
        }
        g_e1[row0 + t] = make_float4(__expf(p1), __expf(0.2f * p1), p1, 0.0f);
        float e2p = __expf(p2), e2n = __expf(0.2f * p2);
        float e2p_n = __shfl_down_sync(0xffffffffu, e2p, 1);
        float e2n_n = __shfl_down_sync(0xffffffffu, e2n, 1);
        if ((t & 1) == 0) {
            __half2 a0 = __floats2half2_rn(e2p, e2p_n);
            __half2 b0 = __floats2half2_rn(e2n, e2n_n);
            uint2 e;
            e.x = h2u(a0); e.y = h2u(b0);
            g_lut[(row0 + t) >> 1] = e;
        }
    }
    {
        int row = t >> 3;
        int f0  = (t & 7) * 16;
#pragma unroll
        for (int q = 0; q < 8; q++) {
            __half2 hp;
            hp.x = __float2half_rn(stage[row * 132 + f0 + q * 2]);
            hp.y = __float2half_rn(stage[row * 132 + f0 + q * 2 + 1]);
            *(__half2*)&g_Wh[(size_t)(row0 + row) * FOUT + f0 + q * 2] = hp;
        }
    }
}

// ---------------- Kernel 2 (R14 structure; genA3 max-trick; half-size LUT) ----------------
// 256 CTAs = 64 i-tiles (128 rows) x 4 j-quarters; 256 thr, 2 CTAs/SM.
#define RB     272
#define BTILE  (128 * RB)
#define LUT_OFF (2 * BTILE)
#define K2_SMEM (LUT_OFF + 1024 + 256)

__global__ __launch_bounds__(256, 2) void k2_attn(const int* __restrict__ adj)
{
    extern __shared__ char base[];
    const uint32_t sb = smem_u32(base);

    const int t = threadIdx.x, lane = t & 31, w = t >> 5;   // 8 warps
    const int i0   = (blockIdx.x >> 2) * 128;
    const int q    = blockIdx.x & 3;
    const int jbeg = q * 2048;

    const int mrow0 = w * 16;
    const int cq    = (lane & 3) * 2;

    const int gr0 = i0 + mrow0 + (lane >> 2);
    const int gr1 = gr0 + 8;
    const float4 E0 = g_e1[gr0];
    const float4 E1 = g_e1[gr1];
    const uint32_t rr0 = bcast_h2(E0.y / E0.x);
    const uint32_t rr1 = bcast_h2(E1.y / E1.x);

    float acc[64];
#pragma unroll
    for (int z = 0; z < 64; z++) acc[z] = 0.0f;
    float dden[4] = {0.f, 0.f, 0.f, 0.f};

    const int bj = t >> 4;
    const int bc = t & 15;

    if (t < 128) {
        uint4 z = make_uint4(0x00003C00u, 0u, 0u, 0u);
        *(uint4*)(base + (uint32_t)t * RB + 256) = z;
        *(uint4*)(base + BTILE + (uint32_t)t * RB + 256) = z;
    }

    // ---- prologue ----
    {
#pragma unroll
        for (int p = 0; p < 8; p++) {
            int j = bj + p * 16;
            cp_async16(sb + (uint32_t)j * RB + bc * 16,
                       &g_Wh[(size_t)(jbeg + j) * FOUT + bc * 8]);
        }
        if (t < 32)
            cp_async16(sb + LUT_OFF + t * 16,
                       (const char*)g_lut + (size_t)(jbeg >> 1) * 8 + t * 16);
        CP_COMMIT();
    }
    uint32_t aq[2][4];
#pragma unroll
    for (int s = 0; s < 2; s++) {
        int jc = jbeg + s * 16 + cq;
        aq[s][0] = adj_mask(*(const int2*)&adj[(size_t)gr0 * NN + jc]);
        aq[s][1] = adj_mask(*(const int2*)&adj[(size_t)gr1 * NN + jc]);
        aq[s][2] = adj_mask(*(const int2*)&adj[(size_t)gr0 * NN + jc + 8]);
        aq[s][3] = adj_mask(*(const int2*)&adj[(size_t)gr1 * NN + jc + 8]);
    }
    CP_WAIT0();
    __syncthreads();

    uint32_t Bones[4];
    ldsm_x4_t(Bones, sb + (uint32_t)(lane & 15) * RB + 256 + (uint32_t)(lane >> 4) * 16);

    // ---- main loop: 16 tiles of 128 j ----
    for (int it = 0; it < 16; it++) {
        const uint32_t bbuf = sb + (uint32_t)(it & 1) * BTILE;
        const uint32_t loff = LUT_OFF + (uint32_t)(it & 1) * 512;

        if (it < 15) {
            const int j0n = jbeg + (it + 1) * 128;
            const uint32_t nb = sb + (uint32_t)((it + 1) & 1) * BTILE;
#pragma unroll
            for (int p = 0; p < 8; p++) {
                int j = bj + p * 16;
                cp_async16(nb + (uint32_t)j * RB + bc * 16,
                           &g_Wh[(size_t)(j0n + j) * FOUT + bc * 8]);
            }
            if (t < 32)
                cp_async16(sb + LUT_OFF + (uint32_t)((it + 1) & 1) * 512 + t * 16,
                           (const char*)g_lut + (size_t)(j0n >> 1) * 8 + t * 16);
            CP_COMMIT();
        }

#pragma unroll
        for (int ks = 0; ks < 8; ks++) {
            uint2 L0 = *(const uint2*)(base + loff + (ks * 8 + (lane & 3)) * 8);
            uint2 L1 = *(const uint2*)(base + loff + (ks * 8 + (lane & 3) + 4) * 8);

            uint32_t A[4];
            A[0] = genA3(L0.x, L0.y, rr0, aq[ks & 1][0]);
            A[1] = genA3(L0.x, L0.y, rr1, aq[ks & 1][1]);
            A[2] = genA3(L1.x, L1.y, rr0, aq[ks & 1][2]);
            A[3] = genA3(L1.x, L1.y, rr1, aq[ks & 1][3]);

            {
                int ksg2 = it * 8 + ks + 2;
                if (ksg2 > 127) ksg2 = 127;
                int jc = jbeg + (ksg2 >> 3) * 128 + (ksg2 & 7) * 16 + cq;
                aq[ks & 1][0] = adj_mask(*(const int2*)&adj[(size_t)gr0 * NN + jc]);
                aq[ks & 1][1] = adj_mask(*(const int2*)&adj[(size_t)gr1 * NN + jc]);
                aq[ks & 1][2] = adj_mask(*(const int2*)&adj[(size_t)gr0 * NN + jc + 8]);
                aq[ks & 1][3] = adj_mask(*(const int2*)&adj[(size_t)gr1 * NN + jc + 8]);
            }

            mma_f16(dden, A, Bones[0], Bones[1]);

#pragma unroll
            for (int ng = 0; ng < 8; ng++) {
                uint32_t B[4];
                uint32_t bo = (uint32_t)(ks * 16 + (lane & 15)) * RB +
                              (ng * 16 + (lane >> 4) * 8) * 2;
                ldsm_x4_t(B, bbuf + bo);
                mma_f16(&acc[(ng * 2) * 4],     A, B[0], B[1]);
                mma_f16(&acc[(ng * 2 + 1) * 4], A, B[2], B[3]);
            }
        }
        CP_WAIT0();
        __syncthreads();
    }

    // ---- den writeout (col 0 of ones-mma) ----
    if ((lane & 3) == 0) {
        g_den[(size_t)q * NN + gr0] = dden[0];
        g_den[(size_t)q * NN + gr1] = dden[2];
    }

    // ---- numerator writeout ----
#pragma unroll
    for (int nb = 0; nb < 16; nb++) {
        const float* d = &acc[nb * 4];
        int col = nb * 8 + cq;
        size_t o0 = ((size_t)q * NN + gr0) * FOUT + col;
        size_t o1 = ((size_t)q * NN + gr1) * FOUT + col;
        *(float2*)&g_num[o0] = make_float2(d[0], d[1]);
        *(float2*)&g_num[o1] = make_float2(d[2], d[3]);
    }
}

// ---------------- Kernel 3: combine 4 partials (2 float4/thread) ----------------
__global__ __launch_bounds__(256) void k3_combine(float* __restrict__ out)
{
    const size_t STR = (size_t)NN * FOUT;
    int b = blockIdx.x * 512 + threadIdx.x;
#pragma unroll
    for (int v = 0; v < 2; v++) {
        int idx = b + v * 256;
        int i = idx >> 5;
        float inv = 1.0f / ((g_den[i] + g_den[NN + i]) +
                            (g_den[2 * NN + i] + g_den[3 * NN + i]));
        float4 a0 = *(const float4*)&g_num[(size_t)idx * 4];
        float4 a1 = *(const float4*)&g_num[STR + (size_t)idx * 4];
        float4 a2 = *(const float4*)&g_num[2 * STR + (size_t)idx * 4];
        float4 a3 = *(const float4*)&g_num[3 * STR + (size_t)idx * 4];
        float4 o;
        o.x = ((a0.x + a1.x) + (a2.x + a3.x)) * inv;
        o.y = ((a0.y + a1.y) + (a2.y + a3.y)) * inv;
        o.z = ((a0.z + a1.z) + (a2.z + a3.z)) * inv;
        o.w = ((a0.w + a1.w) + (a2.w + a3.w)) * inv;
        *(float4*)&out[(size_t)idx * 4] = o;
    }
}

// ---------------- launcher ----------------
extern "C" void kernel_launch(void* const* d_in, const int* in_sizes, int n_in,
                              void* d_out, int out_size)
{
    const float* h   = (const float*)d_in[0];
    const int*   adj = (const int*)  d_in[1];
    const float* W   = (const float*)d_in[2];
    const float* a   = (const float*)d_in[3];
    float* out = (float*)d_out;
    (void)in_sizes; (void)n_in; (void)out_size;

    cudaFuncSetAttribute(k1_gemm_s, cudaFuncAttributeMaxDynamicSharedMemorySize, K1_SMEM);
    cudaFuncSetAttribute(k2_attn,  cudaFuncAttributeMaxDynamicSharedMemorySize, K2_SMEM);

    k1_gemm_s<<<NN / 64, 512, K1_SMEM>>>(h, W, a);
    k2_attn<<<(NN / 128) * 4, 256, K2_SMEM>>>(adj);
    k3_combine<<<NN * FOUT / 4 / 512, 256>>>(out);
}